// round 15
// baseline (speedup 1.0000x reference)
#include <cuda_runtime.h>
#include <cuda_fp16.h>
#include <cstdint>

#define NMAX 100000
#define EMAX 1000000

// -------- persistent device scratch --------
__device__ __half  g_hs [2][NMAX * 64]; // scaled messages, fp16, double-buffered
__device__ __half  g_h16[NMAX * 64];    // current layer activations, fp16
__device__ float4  g_hf [NMAX * 16];    // jumping-knowledge accumulator, fp32
__device__ float   g_cnt[NMAX * 3 + 1];
__device__ int     g_rowptr[NMAX];
__device__ int     g_eidx[EMAX];
__device__ __half  g_w16[3 * 128 * 64]; // [convW;resW] per layer, fp16
__device__ __half  g_pw16[64 * 64];     // predW fp16

#define G_ONORM (g_cnt)
#define G_INORM (g_cnt + NMAX)
#define G_FILL  ((int*)(g_cnt + 2 * NMAX))
#define G_BASE  ((int*)(g_cnt + 3 * NMAX))

__device__ __forceinline__ uint32_t s2u(const void* p) {
    uint32_t a;
    asm("{ .reg .u64 t; cvta.to.shared.u64 t, %1; cvt.u32.u64 %0, t; }" : "=r"(a) : "l"(p));
    return a;
}
// swizzled half-index for a [rows][64-half] tile: chunk(16B) XOR row%8
__device__ __forceinline__ int swzh(int row, int c8) {
    return row * 64 + (((c8) ^ (row & 7)) << 3);
}
#define LDSM4(r0,r1,r2,r3,addr) \
    asm volatile("ldmatrix.sync.aligned.m8n8.x4.shared.b16 {%0,%1,%2,%3},[%4];" \
                 : "=r"(r0),"=r"(r1),"=r"(r2),"=r"(r3) : "r"(addr))
#define LDSM4T(r0,r1,r2,r3,addr) \
    asm volatile("ldmatrix.sync.aligned.m8n8.x4.trans.shared.b16 {%0,%1,%2,%3},[%4];" \
                 : "=r"(r0),"=r"(r1),"=r"(r2),"=r"(r3) : "r"(addr))
#define MMA16(d,a0,a1,a2,a3,b0,b1) \
    asm volatile("mma.sync.aligned.m16n8k16.row.col.f32.f16.f16.f32 " \
                 "{%0,%1,%2,%3},{%4,%5,%6,%7},{%8,%9},{%0,%1,%2,%3};" \
                 : "+f"(d[0]),"+f"(d[1]),"+f"(d[2]),"+f"(d[3]) \
                 : "r"(a0),"r"(a1),"r"(a2),"r"(a3),"r"(b0),"r"(b1))

// -------- degrees (2 edges / thread) --------
__global__ void deg_kernel(const int2* __restrict__ src2, const int2* __restrict__ dst2,
                           int e2, int e, const int* __restrict__ src,
                           const int* __restrict__ dst) {
    int i = blockIdx.x * blockDim.x + threadIdx.x;
    if (i < e2) {
        int2 s = src2[i], d = dst2[i];
        atomicAdd(&G_ONORM[s.x], 1.0f);
        atomicAdd(&G_ONORM[s.y], 1.0f);
        atomicAdd(&G_INORM[d.x], 1.0f);
        atomicAdd(&G_INORM[d.y], 1.0f);
    }
    if (i == 0 && (e & 1)) {
        atomicAdd(&G_ONORM[src[e - 1]], 1.0f);
        atomicAdd(&G_INORM[dst[e - 1]], 1.0f);
    }
}

// -------- scan + norms + layer-0 messages (buf0) + weight fp16 conversion --------
__global__ __launch_bounds__(1024)
void scanconv_kernel(const float4* __restrict__ feats4, int n,
                     const float* __restrict__ convW, const float* __restrict__ resW,
                     const float* __restrict__ predW) {
    __shared__ int sd[1024];
    __shared__ int sbase;
    int t = threadIdx.x;
    int i = blockIdx.x * 1024 + t;
    float ci_f = (i < n) ? G_INORM[i] : 0.f;
    int ci = (int)ci_f;
    sd[t] = ci;
    __syncthreads();
#pragma unroll
    for (int off = 1; off < 1024; off <<= 1) {
        int v = (t >= off) ? sd[t - off] : 0;
        __syncthreads();
        sd[t] += v;
        __syncthreads();
    }
    if (t == 1023) sbase = atomicAdd(G_BASE, sd[1023]);
    __syncthreads();
    if (i < n) {
        g_rowptr[i] = sbase + sd[t] - ci;
        float co = G_ONORM[i];
        float on = rsqrtf(fmaxf(co, 1.0f));
        G_ONORM[i] = on;
        G_INORM[i] = rsqrtf(fmaxf(ci_f, 1.0f));
        uint4* dstp = (uint4*)(g_hs[0] + (size_t)i * 64);
#pragma unroll
        for (int j = 0; j < 8; j++) {
            float4 v0 = feats4[(size_t)i * 16 + j * 2];
            float4 v1 = feats4[(size_t)i * 16 + j * 2 + 1];
            __half2 a0 = __floats2half2_rn(v0.x * on, v0.y * on);
            __half2 a1 = __floats2half2_rn(v0.z * on, v0.w * on);
            __half2 a2 = __floats2half2_rn(v1.x * on, v1.y * on);
            __half2 a3 = __floats2half2_rn(v1.z * on, v1.w * on);
            dstp[j] = make_uint4(*(uint32_t*)&a0, *(uint32_t*)&a1,
                                 *(uint32_t*)&a2, *(uint32_t*)&a3);
        }
    }
    if (blockIdx.x == 0) {
        for (int idx = t; idx < 3 * 8192; idx += 1024) {
            int l = idx >> 13, r = idx & 8191;
            int k = r >> 6, c = r & 63;
            float w = (k < 64) ? convW[l * 4096 + k * 64 + c]
                               : resW[l * 4096 + (k - 64) * 64 + c];
            g_w16[idx] = __float2half_rn(w);
        }
        for (int idx = t; idx < 4096; idx += 1024)
            g_pw16[idx] = __float2half_rn(predW[idx]);
    }
}

// -------- CSR bucket fill (2 edges / thread) --------
__global__ void fill_kernel(const int2* __restrict__ src2, const int2* __restrict__ dst2,
                            int e2, int e, const int* __restrict__ src,
                            const int* __restrict__ dst) {
    int i = blockIdx.x * blockDim.x + threadIdx.x;
    if (i < e2) {
        int2 s = src2[i], d = dst2[i];
        int p0 = atomicAdd(&G_FILL[d.x], 1);
        g_eidx[g_rowptr[d.x] + p0] = s.x;
        int p1 = atomicAdd(&G_FILL[d.y], 1);
        g_eidx[g_rowptr[d.y] + p1] = s.y;
    }
    if (i == 0 && (e & 1)) {
        int d = dst[e - 1];
        int p = atomicAdd(&G_FILL[d], 1);
        g_eidx[g_rowptr[d] + p] = src[e - 1];
    }
}

__device__ __forceinline__ void acc_halfs(float acc[8], uint4 u) {
    __half2 h0 = *(__half2*)&u.x, h1 = *(__half2*)&u.y;
    __half2 h2 = *(__half2*)&u.z, h3 = *(__half2*)&u.w;
    float2 f0 = __half22float2(h0), f1 = __half22float2(h1);
    float2 f2 = __half22float2(h2), f3 = __half22float2(h3);
    acc[0] += f0.x; acc[1] += f0.y; acc[2] += f1.x; acc[3] += f1.y;
    acc[4] += f2.x; acc[5] += f2.y; acc[6] += f3.x; acc[7] += f3.y;
}

// ===== fused: gather-agg + 2-pass HMMA (K-split) + LN + relu (+ pred), 256 thr =========
__global__ __launch_bounds__(256, 5)
void fused_kernel(const float4* __restrict__ feats4,
                  const float* __restrict__ conv_b, const float* __restrict__ res_b,
                  const float* __restrict__ ln_g,  const float* __restrict__ ln_b,
                  const float* __restrict__ pred_b,
                  float* __restrict__ out, int n, int layer)
{
    extern __shared__ __align__(16) char smraw[];
    __half* A16 = (__half*)smraw;            // [128][64] swizzled; staged per K-pass + output
    __half* W16 = A16 + 128 * 64;            // [128][64] swizzled
    float*  sbb = (float*)(W16 + 128 * 64);
    float*  sgg = sbb + 64;
    float*  slb = sgg + 64;
    float*  spb = slb + 64;

    int t = threadIdx.x;
    int lane = t & 31, warp = t >> 5;       // 8 warps
    int base = blockIdx.x * 128;
    int do_pred = (layer == 2);
    const __half* hs_rd = g_hs[layer & 1];
    __half*       hs_wr = g_hs[(layer + 1) & 1];

    if (t < 64) {
        sbb[t] = conv_b[t] + res_b[t];
        sgg[t] = ln_g[t];
        slb[t] = ln_b[t];
        spb[t] = pred_b[t];
    }
    // W16 <- full [convW;resW] (128 k-rows x 64), swizzled
    {
        const uint4* wsrc = (const uint4*)(g_w16 + layer * 8192);
        for (int i = t; i < 1024; i += 256) {
            int k = i >> 3, c8 = i & 7;
            *(uint4*)(W16 + swzh(k, c8)) = wsrc[k * 8 + c8];
        }
    }

    // MMA lane addressing (constant across passes)
    int arow = warp * 16 + (lane & 15);
    uint32_t aBase = s2u(A16) + arow * 128;          // row * 64 halves * 2B
    int axor = arow & 7;
    int ahalf = lane >> 4;                            // 0/1 chunk offset
    uint32_t wBase = s2u(W16);
    int brlo = lane & 15;
    int bhalf = lane >> 4;

    float acc[8][4];
#pragma unroll
    for (int nt = 0; nt < 8; nt++)
#pragma unroll
        for (int c = 0; c < 4; c++) acc[nt][c] = 0.f;

    // ======== PASS 1: A = CSR gather-aggregate * in_norm (features 0..63) ========
    {
        int q = t & 7, grp = t >> 3;   // 32 groups of 8 lanes
#pragma unroll
        for (int j = 0; j < 4; j++) {
            int row = j * 32 + grp;
            int node = base + row;
            float ag[8];
#pragma unroll
            for (int c = 0; c < 8; c++) ag[c] = 0.f;
            if (node < n) {
                int beg = g_rowptr[node];
                int end = beg + G_FILL[node];
                int i = beg;
                for (; i + 4 <= end; i += 4) {
                    int s0 = __ldg(g_eidx + i);
                    int s1 = __ldg(g_eidx + i + 1);
                    int s2 = __ldg(g_eidx + i + 2);
                    int s3 = __ldg(g_eidx + i + 3);
                    uint4 u0 = *(const uint4*)(hs_rd + (size_t)s0 * 64 + q * 8);
                    uint4 u1 = *(const uint4*)(hs_rd + (size_t)s1 * 64 + q * 8);
                    uint4 u2 = *(const uint4*)(hs_rd + (size_t)s2 * 64 + q * 8);
                    uint4 u3 = *(const uint4*)(hs_rd + (size_t)s3 * 64 + q * 8);
                    acc_halfs(ag, u0);
                    acc_halfs(ag, u1);
                    acc_halfs(ag, u2);
                    acc_halfs(ag, u3);
                }
                if (i + 2 <= end) {
                    int s0 = __ldg(g_eidx + i);
                    int s1 = __ldg(g_eidx + i + 1);
                    uint4 u0 = *(const uint4*)(hs_rd + (size_t)s0 * 64 + q * 8);
                    uint4 u1 = *(const uint4*)(hs_rd + (size_t)s1 * 64 + q * 8);
                    acc_halfs(ag, u0);
                    acc_halfs(ag, u1);
                    i += 2;
                }
                if (i < end) {
                    int s0 = __ldg(g_eidx + i);
                    uint4 u0 = *(const uint4*)(hs_rd + (size_t)s0 * 64 + q * 8);
                    acc_halfs(ag, u0);
                }
                float nn = G_INORM[node];
#pragma unroll
                for (int c = 0; c < 8; c++) ag[c] *= nn;
            }
            __half2 p0 = __floats2half2_rn(ag[0], ag[1]);
            __half2 p1 = __floats2half2_rn(ag[2], ag[3]);
            __half2 p2 = __floats2half2_rn(ag[4], ag[5]);
            __half2 p3 = __floats2half2_rn(ag[6], ag[7]);
            *(uint4*)(A16 + swzh(row, q)) =
                make_uint4(*(uint32_t*)&p0, *(uint32_t*)&p1,
                           *(uint32_t*)&p2, *(uint32_t*)&p3);
        }
    }
    __syncthreads();

    // mma pass 1: K=64 against W rows 0..63 (convW)
#pragma unroll
    for (int ks = 0; ks < 4; ks++) {
        uint32_t a0, a1, a2, a3;
        LDSM4(a0, a1, a2, a3, aBase + (((2 * ks + ahalf) ^ axor) << 4));
#pragma unroll
        for (int g = 0; g < 4; g++) {
            int brow = ks * 16 + brlo;
            uint32_t b0, b1, b2, b3;
            LDSM4T(b0, b1, b2, b3, wBase + brow * 128 + (((2 * g + bhalf) ^ (brow & 7)) << 4));
            MMA16(acc[2 * g],     a0, a1, a2, a3, b0, b1);
            MMA16(acc[2 * g + 1], a0, a1, a2, a3, b2, b3);
        }
    }
    __syncthreads();

    // ======== PASS 2: A = h (features 0..63) ========
    {
        int row = t >> 1;
        int node = base + row;
        int c8b = (t & 1) * 4;
        if (node < n) {
            if (layer == 0) {
#pragma unroll
                for (int c8 = c8b; c8 < c8b + 4; c8++) {
                    float4 v0 = feats4[(size_t)node * 16 + c8 * 2];
                    float4 v1 = feats4[(size_t)node * 16 + c8 * 2 + 1];
                    __half2 a0 = __floats2half2_rn(v0.x, v0.y);
                    __half2 a1 = __floats2half2_rn(v0.z, v0.w);
                    __half2 a2 = __floats2half2_rn(v1.x, v1.y);
                    __half2 a3 = __floats2half2_rn(v1.z, v1.w);
                    *(uint4*)(A16 + swzh(row, c8)) =
                        make_uint4(*(uint32_t*)&a0, *(uint32_t*)&a1,
                                   *(uint32_t*)&a2, *(uint32_t*)&a3);
                }
            } else {
                const uint4* hsrc = (const uint4*)(g_h16 + (size_t)node * 64);
#pragma unroll
                for (int c8 = c8b; c8 < c8b + 4; c8++)
                    *(uint4*)(A16 + swzh(row, c8)) = hsrc[c8];
            }
        } else {
            uint4 z = make_uint4(0, 0, 0, 0);
#pragma unroll
            for (int c8 = c8b; c8 < c8b + 4; c8++)
                *(uint4*)(A16 + swzh(row, c8)) = z;
        }
    }
    __syncthreads();

    // mma pass 2: K=64 against W rows 64..127 (resW), accumulate
#pragma unroll
    for (int ks = 0; ks < 4; ks++) {
        uint32_t a0, a1, a2, a3;
        LDSM4(a0, a1, a2, a3, aBase + (((2 * ks + ahalf) ^ axor) << 4));
#pragma unroll
        for (int g = 0; g < 4; g++) {
            int brow = 64 + ks * 16 + brlo;
            uint32_t b0, b1, b2, b3;
            LDSM4T(b0, b1, b2, b3, wBase + brow * 128 + (((2 * g + bhalf) ^ (brow & 7)) << 4));
            MMA16(acc[2 * g],     a0, a1, a2, a3, b0, b1);
            MMA16(acc[2 * g + 1], a0, a1, a2, a3, b2, b3);
        }
    }
    __syncthreads();   // A16 about to be reused as output staging

    // ---- epilogue: bias + LN (quad reduce) + relu, stage fp16 into A16 ----
    {
        float s1 = 0.f, q1 = 0.f, s2 = 0.f, q2 = 0.f;
#pragma unroll
        for (int nt = 0; nt < 8; nt++) {
            int c0 = nt * 8 + (lane & 3) * 2;
            float b0 = sbb[c0], b1 = sbb[c0 + 1];
            float x0 = acc[nt][0] + b0, x1 = acc[nt][1] + b1;
            float y0 = acc[nt][2] + b0, y1 = acc[nt][3] + b1;
            s1 += x0 + x1; q1 += x0 * x0 + x1 * x1;
            s2 += y0 + y1; q2 += y0 * y0 + y1 * y1;
        }
#pragma unroll
        for (int m = 1; m < 4; m <<= 1) {
            s1 += __shfl_xor_sync(0xffffffffu, s1, m);
            q1 += __shfl_xor_sync(0xffffffffu, q1, m);
            s2 += __shfl_xor_sync(0xffffffffu, s2, m);
            q2 += __shfl_xor_sync(0xffffffffu, q2, m);
        }
        float mu1 = s1 * (1.f / 64.f), v1 = q1 * (1.f / 64.f) - mu1 * mu1;
        float mu2 = s2 * (1.f / 64.f), v2 = q2 * (1.f / 64.f) - mu2 * mu2;
        float inv1 = rsqrtf(v1 + 1e-5f), inv2 = rsqrtf(v2 + 1e-5f);
        int R1 = warp * 16 + (lane >> 2);
        int R2 = R1 + 8;
#pragma unroll
        for (int nt = 0; nt < 8; nt++) {
            int c0 = nt * 8 + (lane & 3) * 2;
            float b0 = sbb[c0], b1 = sbb[c0 + 1];
            float g0 = sgg[c0], g1 = sgg[c0 + 1];
            float l0 = slb[c0], l1 = slb[c0 + 1];
            float o0 = fmaxf((acc[nt][0] + b0 - mu1) * inv1 * g0 + l0, 0.f);
            float o1 = fmaxf((acc[nt][1] + b1 - mu1) * inv1 * g1 + l1, 0.f);
            float o2 = fmaxf((acc[nt][2] + b0 - mu2) * inv2 * g0 + l0, 0.f);
            float o3 = fmaxf((acc[nt][3] + b1 - mu2) * inv2 * g1 + l1, 0.f);
            __half2 ha = __floats2half2_rn(o0, o1);
            __half2 hb = __floats2half2_rn(o2, o3);
            *(__half2*)(A16 + R1 * 64 + (((c0 >> 3) ^ (R1 & 7)) << 3) + (c0 & 7)) = ha;
            *(__half2*)(A16 + R2 * 64 + (((c0 >> 3) ^ (R2 & 7)) << 3) + (c0 & 7)) = hb;
        }
    }
    __syncthreads();

    // ---- copy phase: half-row per thread -> h16 / hs_wr / hf  (or pred staging) ----
    {
        int row = t >> 1;
        int node = base + row;
        int c8b = (t & 1) * 4;
        if (node < n) {
            float4* fp = ((float4*)g_hf) + (size_t)node * 16;
            if (!do_pred) {
                float on = G_ONORM[node];
                __half2 on2 = __floats2half2_rn(on, on);
                uint4* hp = (uint4*)(g_h16 + (size_t)node * 64);
                uint4* sp = (uint4*)(hs_wr + (size_t)node * 64);
#pragma unroll
                for (int c8 = c8b; c8 < c8b + 4; c8++) {
                    uint4 u = *(uint4*)(A16 + swzh(row, c8));
                    hp[c8] = u;
                    __half2 h0 = *(__half2*)&u.x, h1 = *(__half2*)&u.y;
                    __half2 h2 = *(__half2*)&u.z, h3 = *(__half2*)&u.w;
                    __half2 m0 = __hmul2(h0, on2), m1 = __hmul2(h1, on2);
                    __half2 m2 = __hmul2(h2, on2), m3 = __hmul2(h3, on2);
                    sp[c8] = make_uint4(*(uint32_t*)&m0, *(uint32_t*)&m1,
                                        *(uint32_t*)&m2, *(uint32_t*)&m3);
                    float2 f0 = __half22float2(h0), f1 = __half22float2(h1);
                    float2 f2 = __half22float2(h2), f3 = __half22float2(h3);
                    float4 lo = make_float4(f0.x, f0.y, f1.x, f1.y);
                    float4 hi = make_float4(f2.x, f2.y, f3.x, f3.y);
                    if (layer == 0) {
                        fp[c8 * 2] = lo; fp[c8 * 2 + 1] = hi;
                    } else {
                        float4 p0 = fp[c8 * 2], p1 = fp[c8 * 2 + 1];
                        p0.x += lo.x; p0.y += lo.y; p0.z += lo.z; p0.w += lo.w;
                        p1.x += hi.x; p1.y += hi.y; p1.z += hi.z; p1.w += hi.w;
                        fp[c8 * 2] = p0; fp[c8 * 2 + 1] = p1;
                    }
                }
            } else {
#pragma unroll
                for (int c8 = c8b; c8 < c8b + 4; c8++) {
                    uint4 u = *(uint4*)(A16 + swzh(row, c8));
                    __half2 h0 = *(__half2*)&u.x, h1 = *(__half2*)&u.y;
                    __half2 h2 = *(__half2*)&u.z, h3 = *(__half2*)&u.w;
                    float2 f0 = __half22float2(h0), f1 = __half22float2(h1);
                    float2 f2 = __half22float2(h2), f3 = __half22float2(h3);
                    float4 p0 = fp[c8 * 2], p1 = fp[c8 * 2 + 1];
                    __half2 r0 = __floats2half2_rn(p0.x + f0.x, p0.y + f0.y);
                    __half2 r1 = __floats2half2_rn(p0.z + f1.x, p0.w + f1.y);
                    __half2 r2 = __floats2half2_rn(p1.x + f2.x, p1.y + f2.y);
                    __half2 r3 = __floats2half2_rn(p1.z + f3.x, p1.w + f3.y);
                    *(uint4*)(A16 + swzh(row, c8)) =
                        make_uint4(*(uint32_t*)&r0, *(uint32_t*)&r1,
                                   *(uint32_t*)&r2, *(uint32_t*)&r3);
                }
            }
        }
    }
    if (!do_pred) return;
    __syncthreads();

    // ---- inline pred GEMM: out = h_final @ predW + pred_b (K=64, HMMA) ----
    {
        const uint4* pw = (const uint4*)g_pw16;
        for (int i = t; i < 512; i += 256) {
            int k = i >> 3, c8 = i & 7;
            *(uint4*)(W16 + swzh(k, c8)) = pw[k * 8 + c8];
        }
    }
    __syncthreads();

#pragma unroll
    for (int nt = 0; nt < 8; nt++)
#pragma unroll
        for (int c = 0; c < 4; c++) acc[nt][c] = 0.f;

#pragma unroll
    for (int ks = 0; ks < 4; ks++) {
        uint32_t a0, a1, a2, a3;
        LDSM4(a0, a1, a2, a3, aBase + (((2 * ks + ahalf) ^ axor) << 4));
#pragma unroll
        for (int g = 0; g < 4; g++) {
            int brow = ks * 16 + brlo;
            uint32_t b0, b1, b2, b3;
            LDSM4T(b0, b1, b2, b3, wBase + brow * 128 + (((2 * g + bhalf) ^ (brow & 7)) << 4));
            MMA16(acc[2 * g],     a0, a1, a2, a3, b0, b1);
            MMA16(acc[2 * g + 1], a0, a1, a2, a3, b2, b3);
        }
    }

    {
        int R = warp * 16 + (lane >> 2);
        int nd1 = base + R, nd2 = base + R + 8;
#pragma unroll
        for (int nt = 0; nt < 8; nt++) {
            int c0 = nt * 8 + (lane & 3) * 2;
            float b0 = spb[c0], b1 = spb[c0 + 1];
            if (nd1 < n)
                *(float2*)(out + (size_t)nd1 * 64 + c0) =
                    make_float2(acc[nt][0] + b0, acc[nt][1] + b1);
            if (nd2 < n)
                *(float2*)(out + (size_t)nd2 * 64 + c0) =
                    make_float2(acc[nt][2] + b0, acc[nt][3] + b1);
        }
    }
}

// -------- host entry --------
extern "C" void kernel_launch(void* const* d_in, const int* in_sizes, int n_in,
                              void* d_out, int out_size)
{
    const float* feats  = (const float*)d_in[0];
    const int*   src    = (const int*)  d_in[1];
    const int*   dst    = (const int*)  d_in[2];
    const float* convW  = (const float*)d_in[3];
    const float* conv_b = (const float*)d_in[4];
    const float* resW   = (const float*)d_in[5];
    const float* res_b  = (const float*)d_in[6];
    const float* ln_g   = (const float*)d_in[7];
    const float* ln_b   = (const float*)d_in[8];
    const float* predW  = (const float*)d_in[9];
    const float* pred_b = (const float*)d_in[10];

    int n = in_sizes[0] / 64;
    int e = in_sizes[1];
    int e2 = e / 2;
    int nb = (n + 1023) / 1024;

    const int smem_fused = (128 * 64 + 128 * 64) * 2 + 4 * 64 * 4;  // 33792 B
    cudaFuncSetAttribute(fused_kernel, cudaFuncAttributeMaxDynamicSharedMemorySize, smem_fused);

    void* p_cnt;
    cudaGetSymbolAddress(&p_cnt, g_cnt);
    cudaMemsetAsync(p_cnt, 0, (NMAX * 3 + 1) * sizeof(float));

    deg_kernel<<<(e2 + 255) / 256, 256>>>((const int2*)src, (const int2*)dst, e2, e, src, dst);
    scanconv_kernel<<<nb, 1024>>>((const float4*)feats, n, convW, resW, predW);
    fill_kernel<<<(e2 + 255) / 256, 256>>>((const int2*)src, (const int2*)dst, e2, e, src, dst);

    int gb = (n + 127) / 128;
    for (int l = 0; l < 3; l++) {
        fused_kernel<<<gb, 256, smem_fused>>>((const float4*)feats,
                                              conv_b + l * 64, res_b + l * 64,
                                              ln_g + l * 64, ln_b + l * 64,
                                              pred_b, (float*)d_out, n, l);
    }
}

// round 17
// speedup vs baseline: 1.2015x; 1.2015x over previous
#include <cuda_runtime.h>
#include <cuda_fp16.h>
#include <cstdint>

#define NMAX 100000
#define EMAX 1000000

// -------- persistent device scratch --------
__device__ __half  g_hs [2][NMAX * 64]; // scaled messages, fp16, double-buffered
__device__ __half  g_h16[NMAX * 64];    // current layer activations, fp16
__device__ float4  g_hf [NMAX * 16];    // jumping-knowledge accumulator, fp32
__device__ float   g_cnt[NMAX * 3 + 1];
__device__ int     g_rowptr[NMAX];
__device__ int     g_eidx[EMAX];
__device__ __half  g_w16[3 * 128 * 64]; // [convW;resW] per layer, fp16
__device__ __half  g_pw16[64 * 64];     // predW fp16

#define G_ONORM (g_cnt)
#define G_INORM (g_cnt + NMAX)
#define G_FILL  ((int*)(g_cnt + 2 * NMAX))
#define G_BASE  ((int*)(g_cnt + 3 * NMAX))

__device__ __forceinline__ uint32_t s2u(const void* p) {
    uint32_t a;
    asm("{ .reg .u64 t; cvta.to.shared.u64 t, %1; cvt.u32.u64 %0, t; }" : "=r"(a) : "l"(p));
    return a;
}
// swizzled half-index, A tile [64 rows][128 halves]: 16B chunk c (0..15) XOR row%8
__device__ __forceinline__ int swzA(int row, int c) {
    return row * 128 + ((c ^ (row & 7)) << 3);
}
// swizzled half-index, W tile [rows][64 halves]: chunk c8 (0..7) XOR row%8
__device__ __forceinline__ int swzW(int row, int c8) {
    return row * 64 + ((c8 ^ (row & 7)) << 3);
}
#define LDSM4(r0,r1,r2,r3,addr) \
    asm volatile("ldmatrix.sync.aligned.m8n8.x4.shared.b16 {%0,%1,%2,%3},[%4];" \
                 : "=r"(r0),"=r"(r1),"=r"(r2),"=r"(r3) : "r"(addr))
#define LDSM4T(r0,r1,r2,r3,addr) \
    asm volatile("ldmatrix.sync.aligned.m8n8.x4.trans.shared.b16 {%0,%1,%2,%3},[%4];" \
                 : "=r"(r0),"=r"(r1),"=r"(r2),"=r"(r3) : "r"(addr))
#define MMA16(d,a0,a1,a2,a3,b0,b1) \
    asm volatile("mma.sync.aligned.m16n8k16.row.col.f32.f16.f16.f32 " \
                 "{%0,%1,%2,%3},{%4,%5,%6,%7},{%8,%9},{%0,%1,%2,%3};" \
                 : "+f"(d[0]),"+f"(d[1]),"+f"(d[2]),"+f"(d[3]) \
                 : "r"(a0),"r"(a1),"r"(a2),"r"(a3),"r"(b0),"r"(b1))

// -------- degrees (2 edges / thread) --------
__global__ void deg_kernel(const int2* __restrict__ src2, const int2* __restrict__ dst2,
                           int e2, int e, const int* __restrict__ src,
                           const int* __restrict__ dst) {
    int i = blockIdx.x * blockDim.x + threadIdx.x;
    if (i < e2) {
        int2 s = src2[i], d = dst2[i];
        atomicAdd(&G_ONORM[s.x], 1.0f);
        atomicAdd(&G_ONORM[s.y], 1.0f);
        atomicAdd(&G_INORM[d.x], 1.0f);
        atomicAdd(&G_INORM[d.y], 1.0f);
    }
    if (i == 0 && (e & 1)) {
        atomicAdd(&G_ONORM[src[e - 1]], 1.0f);
        atomicAdd(&G_INORM[dst[e - 1]], 1.0f);
    }
}

// -------- scan + norms + layer-0 messages (buf0) + weight fp16 conversion --------
__global__ __launch_bounds__(1024)
void scanconv_kernel(const float4* __restrict__ feats4, int n,
                     const float* __restrict__ convW, const float* __restrict__ resW,
                     const float* __restrict__ predW) {
    __shared__ int sd[1024];
    __shared__ int sbase;
    int t = threadIdx.x;
    int i = blockIdx.x * 1024 + t;
    float ci_f = (i < n) ? G_INORM[i] : 0.f;
    int ci = (int)ci_f;
    sd[t] = ci;
    __syncthreads();
#pragma unroll
    for (int off = 1; off < 1024; off <<= 1) {
        int v = (t >= off) ? sd[t - off] : 0;
        __syncthreads();
        sd[t] += v;
        __syncthreads();
    }
    if (t == 1023) sbase = atomicAdd(G_BASE, sd[1023]);
    __syncthreads();
    if (i < n) {
        g_rowptr[i] = sbase + sd[t] - ci;
        float co = G_ONORM[i];
        float on = rsqrtf(fmaxf(co, 1.0f));
        G_ONORM[i] = on;
        G_INORM[i] = rsqrtf(fmaxf(ci_f, 1.0f));
        uint4* dstp = (uint4*)(g_hs[0] + (size_t)i * 64);
#pragma unroll
        for (int j = 0; j < 8; j++) {
            float4 v0 = feats4[(size_t)i * 16 + j * 2];
            float4 v1 = feats4[(size_t)i * 16 + j * 2 + 1];
            __half2 a0 = __floats2half2_rn(v0.x * on, v0.y * on);
            __half2 a1 = __floats2half2_rn(v0.z * on, v0.w * on);
            __half2 a2 = __floats2half2_rn(v1.x * on, v1.y * on);
            __half2 a3 = __floats2half2_rn(v1.z * on, v1.w * on);
            dstp[j] = make_uint4(*(uint32_t*)&a0, *(uint32_t*)&a1,
                                 *(uint32_t*)&a2, *(uint32_t*)&a3);
        }
    }
    if (blockIdx.x == 0) {
        for (int idx = t; idx < 3 * 8192; idx += 1024) {
            int l = idx >> 13, r = idx & 8191;
            int k = r >> 6, c = r & 63;
            float w = (k < 64) ? convW[l * 4096 + k * 64 + c]
                               : resW[l * 4096 + (k - 64) * 64 + c];
            g_w16[idx] = __float2half_rn(w);
        }
        for (int idx = t; idx < 4096; idx += 1024)
            g_pw16[idx] = __float2half_rn(predW[idx]);
    }
}

// -------- CSR bucket fill (2 edges / thread) --------
__global__ void fill_kernel(const int2* __restrict__ src2, const int2* __restrict__ dst2,
                            int e2, int e, const int* __restrict__ src,
                            const int* __restrict__ dst) {
    int i = blockIdx.x * blockDim.x + threadIdx.x;
    if (i < e2) {
        int2 s = src2[i], d = dst2[i];
        int p0 = atomicAdd(&G_FILL[d.x], 1);
        g_eidx[g_rowptr[d.x] + p0] = s.x;
        int p1 = atomicAdd(&G_FILL[d.y], 1);
        g_eidx[g_rowptr[d.y] + p1] = s.y;
    }
    if (i == 0 && (e & 1)) {
        int d = dst[e - 1];
        int p = atomicAdd(&G_FILL[d], 1);
        g_eidx[g_rowptr[d] + p] = src[e - 1];
    }
}

__device__ __forceinline__ uint4 hadd4(uint4 a, uint4 b) {
    __half2 r0 = __hadd2(*(__half2*)&a.x, *(__half2*)&b.x);
    __half2 r1 = __hadd2(*(__half2*)&a.y, *(__half2*)&b.y);
    __half2 r2 = __hadd2(*(__half2*)&a.z, *(__half2*)&b.z);
    __half2 r3 = __hadd2(*(__half2*)&a.w, *(__half2*)&b.w);
    return make_uint4(*(uint32_t*)&r0, *(uint32_t*)&r1, *(uint32_t*)&r2, *(uint32_t*)&r3);
}
__device__ __forceinline__ void acc_halfs(float acc[8], uint4 u) {
    __half2 h0 = *(__half2*)&u.x, h1 = *(__half2*)&u.y;
    __half2 h2 = *(__half2*)&u.z, h3 = *(__half2*)&u.w;
    float2 f0 = __half22float2(h0), f1 = __half22float2(h1);
    float2 f2 = __half22float2(h2), f3 = __half22float2(h3);
    acc[0] += f0.x; acc[1] += f0.y; acc[2] += f1.x; acc[3] += f1.y;
    acc[4] += f2.x; acc[5] += f2.y; acc[6] += f3.x; acc[7] += f3.y;
}

// ===== fused: gather-agg + HMMA (M=64 tile, N-split warps) + LN + relu (+ pred) =======
__global__ __launch_bounds__(256, 5)
void fused_kernel(const float4* __restrict__ feats4,
                  const float* __restrict__ conv_b, const float* __restrict__ res_b,
                  const float* __restrict__ ln_g,  const float* __restrict__ ln_b,
                  const float* __restrict__ pred_b,
                  float* __restrict__ out, int n, int layer)
{
    extern __shared__ __align__(16) char smraw[];
    __half* A16 = (__half*)smraw;            // [64][128] swizzled; reused as output staging
    __half* W16 = A16 + 64 * 128;            // [128][64] swizzled
    float*  sbb = (float*)(W16 + 128 * 64);
    float*  sgg = sbb + 64;
    float*  slb = sgg + 64;
    float*  spb = slb + 64;
    float*  sred = spb + 64;                 // [64 rows][2 halves][2] LN partials

    int t = threadIdx.x;
    int lane = t & 31, warp = t >> 5;       // 8 warps
    int base = blockIdx.x * 64;
    int do_pred = (layer == 2);
    const __half* hs_rd = g_hs[layer & 1];
    __half*       hs_wr = g_hs[(layer + 1) & 1];

    int mrow = (warp & 3) * 16;             // warp's row strip
    int chalf = warp >> 2;                  // warp's 32-col half (0/1)

    if (t < 64) {
        sbb[t] = conv_b[t] + res_b[t];
        sgg[t] = ln_g[t];
        slb[t] = ln_b[t];
        spb[t] = pred_b[t];
    }
    // W16 <- full [convW;resW] (128 k-rows x 64), swizzled
    {
        const uint4* wsrc = (const uint4*)(g_w16 + layer * 8192);
        for (int i = t; i < 1024; i += 256) {
            int k = i >> 3, c8 = i & 7;
            *(uint4*)(W16 + swzW(k, c8)) = wsrc[k * 8 + c8];
        }
    }
    // A chunks 8..15: h (feats layer 0, g_h16 otherwise); 4 threads per row
    {
        int row = t >> 2;
        int node = base + row;
        int fc8b = (t & 3) * 2;
        if (node < n) {
            if (layer == 0) {
#pragma unroll
                for (int fc8 = fc8b; fc8 < fc8b + 2; fc8++) {
                    float4 v0 = feats4[(size_t)node * 16 + fc8 * 2];
                    float4 v1 = feats4[(size_t)node * 16 + fc8 * 2 + 1];
                    __half2 a0 = __floats2half2_rn(v0.x, v0.y);
                    __half2 a1 = __floats2half2_rn(v0.z, v0.w);
                    __half2 a2 = __floats2half2_rn(v1.x, v1.y);
                    __half2 a3 = __floats2half2_rn(v1.z, v1.w);
                    *(uint4*)(A16 + swzA(row, 8 + fc8)) =
                        make_uint4(*(uint32_t*)&a0, *(uint32_t*)&a1,
                                   *(uint32_t*)&a2, *(uint32_t*)&a3);
                }
            } else {
                const uint4* hsrc = (const uint4*)(g_h16 + (size_t)node * 64);
#pragma unroll
                for (int fc8 = fc8b; fc8 < fc8b + 2; fc8++)
                    *(uint4*)(A16 + swzA(row, 8 + fc8)) = hsrc[fc8];
            }
        } else {
            uint4 z = make_uint4(0, 0, 0, 0);
#pragma unroll
            for (int fc8 = fc8b; fc8 < fc8b + 2; fc8++)
                *(uint4*)(A16 + swzA(row, 8 + fc8)) = z;
        }
    }
    // A chunks 0..7: CSR gather-aggregate * in_norm; 32 groups of 8 lanes, 2 rows each
    {
        int q = t & 7, grp = t >> 3;
#pragma unroll
        for (int j = 0; j < 2; j++) {
            int row = j * 32 + grp;
            int node = base + row;
            float ag[8];
#pragma unroll
            for (int c = 0; c < 8; c++) ag[c] = 0.f;
            if (node < n) {
                int beg = g_rowptr[node];
                int end = beg + G_FILL[node];
                int i = beg;
                for (; i + 4 <= end; i += 4) {
                    int s0 = __ldg(g_eidx + i);
                    int s1 = __ldg(g_eidx + i + 1);
                    int s2 = __ldg(g_eidx + i + 2);
                    int s3 = __ldg(g_eidx + i + 3);
                    uint4 u0 = *(const uint4*)(hs_rd + (size_t)s0 * 64 + q * 8);
                    uint4 u1 = *(const uint4*)(hs_rd + (size_t)s1 * 64 + q * 8);
                    uint4 u2 = *(const uint4*)(hs_rd + (size_t)s2 * 64 + q * 8);
                    uint4 u3 = *(const uint4*)(hs_rd + (size_t)s3 * 64 + q * 8);
                    acc_halfs(ag, hadd4(u0, u1));   // fp16 pair-sum, fp32 accumulate
                    acc_halfs(ag, hadd4(u2, u3));
                }
                if (i + 2 <= end) {
                    int s0 = __ldg(g_eidx + i);
                    int s1 = __ldg(g_eidx + i + 1);
                    uint4 u0 = *(const uint4*)(hs_rd + (size_t)s0 * 64 + q * 8);
                    uint4 u1 = *(const uint4*)(hs_rd + (size_t)s1 * 64 + q * 8);
                    acc_halfs(ag, hadd4(u0, u1));
                    i += 2;
                }
                if (i < end) {
                    int s0 = __ldg(g_eidx + i);
                    uint4 u0 = *(const uint4*)(hs_rd + (size_t)s0 * 64 + q * 8);
                    acc_halfs(ag, u0);
                }
                float nn = G_INORM[node];
#pragma unroll
                for (int c = 0; c < 8; c++) ag[c] *= nn;
            }
            __half2 p0 = __floats2half2_rn(ag[0], ag[1]);
            __half2 p1 = __floats2half2_rn(ag[2], ag[3]);
            __half2 p2 = __floats2half2_rn(ag[4], ag[5]);
            __half2 p3 = __floats2half2_rn(ag[6], ag[7]);
            *(uint4*)(A16 + swzA(row, q)) =
                make_uint4(*(uint32_t*)&p0, *(uint32_t*)&p1,
                           *(uint32_t*)&p2, *(uint32_t*)&p3);
        }
    }
    __syncthreads();

    // ---- HMMA: 64x64, K=128; warp = (row strip, col half) ----
    int arow = mrow + (lane & 15);
    uint32_t aBase = s2u(A16) + arow * 256;
    int axor = arow & 7;
    int ahalf = lane >> 4;
    uint32_t wBase = s2u(W16);
    int brlo = lane & 15;
    int bhalf = lane >> 4;

    float acc[4][4];
#pragma unroll
    for (int nt = 0; nt < 4; nt++)
#pragma unroll
        for (int c = 0; c < 4; c++) acc[nt][c] = 0.f;

#pragma unroll
    for (int ks = 0; ks < 8; ks++) {
        uint32_t a0, a1, a2, a3;
        LDSM4(a0, a1, a2, a3, aBase + (((2 * ks + ahalf) ^ axor) << 4));
#pragma unroll
        for (int g = 0; g < 2; g++) {
            int brow = ks * 16 + brlo;
            uint32_t b0, b1, b2, b3;
            LDSM4T(b0, b1, b2, b3,
                   wBase + brow * 128 + (((chalf * 4 + g * 2 + bhalf) ^ (brow & 7)) << 4));
            MMA16(acc[2 * g],     a0, a1, a2, a3, b0, b1);
            MMA16(acc[2 * g + 1], a0, a1, a2, a3, b2, b3);
        }
    }

    // ---- LN partials (32 cols per warp) -> sred ----
    {
        float s1 = 0.f, q1 = 0.f, s2 = 0.f, q2 = 0.f;
#pragma unroll
        for (int nt = 0; nt < 4; nt++) {
            int c0 = chalf * 32 + nt * 8 + (lane & 3) * 2;
            float b0 = sbb[c0], b1 = sbb[c0 + 1];
            float x0 = acc[nt][0] + b0, x1 = acc[nt][1] + b1;
            float y0 = acc[nt][2] + b0, y1 = acc[nt][3] + b1;
            s1 += x0 + x1; q1 += x0 * x0 + x1 * x1;
            s2 += y0 + y1; q2 += y0 * y0 + y1 * y1;
        }
#pragma unroll
        for (int m = 1; m < 4; m <<= 1) {
            s1 += __shfl_xor_sync(0xffffffffu, s1, m);
            q1 += __shfl_xor_sync(0xffffffffu, q1, m);
            s2 += __shfl_xor_sync(0xffffffffu, s2, m);
            q2 += __shfl_xor_sync(0xffffffffu, q2, m);
        }
        if ((lane & 3) == 0) {
            int r1 = mrow + (lane >> 2), r2 = r1 + 8;
            sred[r1 * 4 + chalf * 2]     = s1;
            sred[r1 * 4 + chalf * 2 + 1] = q1;
            sred[r2 * 4 + chalf * 2]     = s2;
            sred[r2 * 4 + chalf * 2 + 1] = q2;
        }
    }
    __syncthreads();   // sred complete; MMA done everywhere; A16 free for staging

    // ---- epilogue: combined LN + relu, stage fp16 into A16 chunks 0..7 ----
    {
        int r1 = mrow + (lane >> 2), r2 = r1 + 8;
        float s1 = sred[r1 * 4] + sred[r1 * 4 + 2];
        float q1 = sred[r1 * 4 + 1] + sred[r1 * 4 + 3];
        float s2 = sred[r2 * 4] + sred[r2 * 4 + 2];
        float q2 = sred[r2 * 4 + 1] + sred[r2 * 4 + 3];
        float mu1 = s1 * (1.f / 64.f), v1 = q1 * (1.f / 64.f) - mu1 * mu1;
        float mu2 = s2 * (1.f / 64.f), v2 = q2 * (1.f / 64.f) - mu2 * mu2;
        float inv1 = rsqrtf(v1 + 1e-5f), inv2 = rsqrtf(v2 + 1e-5f);
#pragma unroll
        for (int nt = 0; nt < 4; nt++) {
            int c0 = chalf * 32 + nt * 8 + (lane & 3) * 2;
            float b0 = sbb[c0], b1 = sbb[c0 + 1];
            float g0 = sgg[c0], g1 = sgg[c0 + 1];
            float l0 = slb[c0], l1 = slb[c0 + 1];
            float o0 = fmaxf((acc[nt][0] + b0 - mu1) * inv1 * g0 + l0, 0.f);
            float o1 = fmaxf((acc[nt][1] + b1 - mu1) * inv1 * g1 + l1, 0.f);
            float o2 = fmaxf((acc[nt][2] + b0 - mu2) * inv2 * g0 + l0, 0.f);
            float o3 = fmaxf((acc[nt][3] + b1 - mu2) * inv2 * g1 + l1, 0.f);
            __half2 ha = __floats2half2_rn(o0, o1);
            __half2 hb = __floats2half2_rn(o2, o3);
            int c8 = chalf * 4 + nt, off = (lane & 3) * 2;
            *(__half2*)(A16 + r1 * 128 + ((c8 ^ (r1 & 7)) << 3) + off) = ha;
            *(__half2*)(A16 + r2 * 128 + ((c8 ^ (r2 & 7)) << 3) + off) = hb;
        }
    }
    __syncthreads();

    // ---- copy phase: 4 threads/row -> h16 / hs_wr / hf  (or pred staging) ----
    {
        int row = t >> 2;
        int node = base + row;
        int c8b = (t & 3) * 2;
        if (node < n) {
            float4* fp = ((float4*)g_hf) + (size_t)node * 16;
            if (!do_pred) {
                float on = G_ONORM[node];
                __half2 on2 = __floats2half2_rn(on, on);
                uint4* hp = (uint4*)(g_h16 + (size_t)node * 64);
                uint4* sp = (uint4*)(hs_wr + (size_t)node * 64);
#pragma unroll
                for (int c8 = c8b; c8 < c8b + 2; c8++) {
                    uint4 u = *(uint4*)(A16 + swzA(row, c8));
                    hp[c8] = u;
                    __half2 h0 = *(__half2*)&u.x, h1 = *(__half2*)&u.y;
                    __half2 h2 = *(__half2*)&u.z, h3 = *(__half2*)&u.w;
                    __half2 m0 = __hmul2(h0, on2), m1 = __hmul2(h1, on2);
                    __half2 m2 = __hmul2(h2, on2), m3 = __hmul2(h3, on2);
                    sp[c8] = make_uint4(*(uint32_t*)&m0, *(uint32_t*)&m1,
                                        *(uint32_t*)&m2, *(uint32_t*)&m3);
                    float2 f0 = __half22float2(h0), f1 = __half22float2(h1);
                    float2 f2 = __half22float2(h2), f3 = __half22float2(h3);
                    float4 lo = make_float4(f0.x, f0.y, f1.x, f1.y);
                    float4 hi = make_float4(f2.x, f2.y, f3.x, f3.y);
                    if (layer == 0) {
                        fp[c8 * 2] = lo; fp[c8 * 2 + 1] = hi;
                    } else {
                        float4 p0 = fp[c8 * 2], p1 = fp[c8 * 2 + 1];
                        p0.x += lo.x; p0.y += lo.y; p0.z += lo.z; p0.w += lo.w;
                        p1.x += hi.x; p1.y += hi.y; p1.z += hi.z; p1.w += hi.w;
                        fp[c8 * 2] = p0; fp[c8 * 2 + 1] = p1;
                    }
                }
            } else {
#pragma unroll
                for (int c8 = c8b; c8 < c8b + 2; c8++) {
                    uint4 u = *(uint4*)(A16 + swzA(row, c8));
                    __half2 h0 = *(__half2*)&u.x, h1 = *(__half2*)&u.y;
                    __half2 h2 = *(__half2*)&u.z, h3 = *(__half2*)&u.w;
                    float2 f0 = __half22float2(h0), f1 = __half22float2(h1);
                    float2 f2 = __half22float2(h2), f3 = __half22float2(h3);
                    float4 p0 = fp[c8 * 2], p1 = fp[c8 * 2 + 1];
                    __half2 r0 = __floats2half2_rn(p0.x + f0.x, p0.y + f0.y);
                    __half2 r1 = __floats2half2_rn(p0.z + f1.x, p0.w + f1.y);
                    __half2 r2 = __floats2half2_rn(p1.x + f2.x, p1.y + f2.y);
                    __half2 r3 = __floats2half2_rn(p1.z + f3.x, p1.w + f3.y);
                    *(uint4*)(A16 + swzA(row, c8)) =
                        make_uint4(*(uint32_t*)&r0, *(uint32_t*)&r1,
                                   *(uint32_t*)&r2, *(uint32_t*)&r3);
                }
            }
        }
    }
    if (!do_pred) return;

    // ---- inline pred GEMM: out = h_final @ predW + pred_b (K=64, HMMA) ----
    {
        const uint4* pw = (const uint4*)g_pw16;
        for (int i = t; i < 512; i += 256) {
            int k = i >> 3, c8 = i & 7;
            *(uint4*)(W16 + swzW(k, c8)) = pw[k * 8 + c8];
        }
    }
    __syncthreads();   // A16 staging + W16 pred weights complete

#pragma unroll
    for (int nt = 0; nt < 4; nt++)
#pragma unroll
        for (int c = 0; c < 4; c++) acc[nt][c] = 0.f;

#pragma unroll
    for (int ks = 0; ks < 4; ks++) {
        uint32_t a0, a1, a2, a3;
        LDSM4(a0, a1, a2, a3, aBase + (((2 * ks + ahalf) ^ axor) << 4));
#pragma unroll
        for (int g = 0; g < 2; g++) {
            int brow = ks * 16 + brlo;
            uint32_t b0, b1, b2, b3;
            LDSM4T(b0, b1, b2, b3,
                   wBase + brow * 128 + (((chalf * 4 + g * 2 + bhalf) ^ (brow & 7)) << 4));
            MMA16(acc[2 * g],     a0, a1, a2, a3, b0, b1);
            MMA16(acc[2 * g + 1], a0, a1, a2, a3, b2, b3);
        }
    }

    {
        int r1 = mrow + (lane >> 2);
        int nd1 = base + r1, nd2 = base + r1 + 8;
#pragma unroll
        for (int nt = 0; nt < 4; nt++) {
            int c0 = chalf * 32 + nt * 8 + (lane & 3) * 2;
            float b0 = spb[c0], b1 = spb[c0 + 1];
            if (nd1 < n)
                *(float2*)(out + (size_t)nd1 * 64 + c0) =
                    make_float2(acc[nt][0] + b0, acc[nt][1] + b1);
            if (nd2 < n)
                *(float2*)(out + (size_t)nd2 * 64 + c0) =
                    make_float2(acc[nt][2] + b0, acc[nt][3] + b1);
        }
    }
}

// -------- host entry --------
extern "C" void kernel_launch(void* const* d_in, const int* in_sizes, int n_in,
                              void* d_out, int out_size)
{
    const float* feats  = (const float*)d_in[0];
    const int*   src    = (const int*)  d_in[1];
    const int*   dst    = (const int*)  d_in[2];
    const float* convW  = (const float*)d_in[3];
    const float* conv_b = (const float*)d_in[4];
    const float* resW   = (const float*)d_in[5];
    const float* res_b  = (const float*)d_in[6];
    const float* ln_g   = (const float*)d_in[7];
    const float* ln_b   = (const float*)d_in[8];
    const float* predW  = (const float*)d_in[9];
    const float* pred_b = (const float*)d_in[10];

    int n = in_sizes[0] / 64;
    int e = in_sizes[1];
    int e2 = e / 2;
    int nb = (n + 1023) / 1024;

    const int smem_fused = (64 * 128 + 128 * 64) * 2 + 4 * 64 * 4 + 64 * 4 * 4;  // 34816 B
    cudaFuncSetAttribute(fused_kernel, cudaFuncAttributeMaxDynamicSharedMemorySize, smem_fused);

    void* p_cnt;
    cudaGetSymbolAddress(&p_cnt, g_cnt);
    cudaMemsetAsync(p_cnt, 0, (NMAX * 3 + 1) * sizeof(float));

    deg_kernel<<<(e2 + 255) / 256, 256>>>((const int2*)src, (const int2*)dst, e2, e, src, dst);
    scanconv_kernel<<<nb, 1024>>>((const float4*)feats, n, convW, resW, predW);
    fill_kernel<<<(e2 + 255) / 256, 256>>>((const int2*)src, (const int2*)dst, e2, e, src, dst);

    int gb = (n + 63) / 64;
    for (int l = 0; l < 3; l++) {
        fused_kernel<<<gb, 256, smem_fused>>>((const float4*)feats,
                                              conv_b + l * 64, res_b + l * 64,
                                              ln_g + l * 64, ln_b + l * 64,
                                              pred_b, (float*)d_out, n, l);
    }
}